// round 12
// baseline (speedup 1.0000x reference)
#include <cuda_runtime.h>

#define T_LEN 2048
#define B_SZ  256
#define HDIM  64
#define Y_SIZE (B_SZ * T_LEN)
#define HALF_OFF (2 * B_SZ * T_LEN)

typedef unsigned long long u64;

// per-half scalar projections: [half][dir*B+batch][t]
__device__ float g_sh[2 * 2 * B_SZ * T_LEN];

__device__ __forceinline__ u64 ffma2(u64 a, u64 b, u64 c) {
    u64 d;
    asm("fma.rn.f32x2 %0, %1, %2, %3;" : "=l"(d) : "l"(a), "l"(b), "l"(c));
    return d;
}
__device__ __forceinline__ u64 fadd2(u64 a, u64 b) {
    u64 d;
    asm("add.rn.f32x2 %0, %1, %2;" : "=l"(d) : "l"(a), "l"(b));
    return d;
}
__device__ __forceinline__ u64 pack2(float lo, float hi) {
    u64 r;
    asm("mov.b64 %0, {%1, %2};" : "=l"(r) : "f"(lo), "f"(hi));
    return r;
}
__device__ __forceinline__ void unpack2(u64 v, float& lo, float& hi) {
    asm("mov.b64 {%0, %1}, %2;" : "=f"(lo), "=f"(hi) : "l"(v));
}
__device__ __forceinline__ float fast_tanh(float z) {
    float e = __expf(2.0f * z);
    return 1.0f - __fdividef(2.0f, e + 1.0f);
}
__device__ __forceinline__ void st_cs(float* p, float v) {
    asm volatile("st.global.cs.f32 [%0], %1;" :: "l"(p), "f"(v) : "memory");
}

__global__ __launch_bounds__(256, 1)
void birnn_kernel(const float* __restrict__ x,
                  const float* __restrict__ w_ih_f, const float* __restrict__ w_hh_f,
                  const float* __restrict__ b_ih_f, const float* __restrict__ b_hh_f,
                  const float* __restrict__ w_ih_b, const float* __restrict__ w_hh_b,
                  const float* __restrict__ b_ih_b, const float* __restrict__ b_hh_b,
                  const float* __restrict__ w_fc,  const float* __restrict__ b_fc,
                  float* __restrict__ out)
{
    __shared__ __align__(16) float xsh[2][T_LEN];      // two batch rows of x
    __shared__ __align__(16) float hbuf[4][2][HDIM];   // per-chain double-buffered h

    const int tid   = threadIdx.x;
    const int wid   = tid >> 5;       // 0..7
    const int lane  = tid & 31;
    const int bb    = blockIdx.x;     // 0..127
    const int chain = wid >> 1;       // 0..3 (warps 2c, 2c+1 cooperate)
    const int half  = wid & 1;        // which 32-row half this warp owns
    const int bl    = chain >> 1;     // batch-local 0/1
    const int dir   = chain & 1;      // 0 fwd, 1 bwd
    const int batch = bb * 2 + bl;
    const int r     = half * 32 + lane;   // owned row 0..63

    // ---- preload the two x rows (contiguous 4096 floats) ----
    {
        const float4* xg = (const float4*)(x + (bb * 2) * T_LEN);
        float4* xs = (float4*)xsh;
        for (int i = tid; i < (2 * T_LEN) / 4; i += 256) xs[i] = xg[i];
    }

    // zero initial hidden state (buffer 0): each warp zeroes its half
    hbuf[chain][0][r] = 0.0f;

    // ---- per-direction parameters ----
    const float* w_ih = dir ? w_ih_b : w_ih_f;
    const float* w_hh = dir ? w_hh_b : w_hh_f;
    const float* b_ih = dir ? b_ih_b : b_ih_f;
    const float* b_hh = dir ? b_hh_b : b_hh_f;

    const float wih  = w_ih[r];
    const float bias = b_ih[r] + b_hh[r];
    const float wfc  = w_fc[r];

    // W_hh row r as 32 packed f32-pairs (64 regs)
    u64 Wp[32];
    {
        const u64* wr = (const u64*)(w_hh + r * HDIM);   // 256B-aligned rows
        #pragma unroll
        for (int k = 0; k < 32; k++) Wp[k] = wr[k];
    }

    float* g_row = g_sh + half * HALF_OFF + (dir * B_SZ + batch) * T_LEN;
    const float* xrow = xsh[bl];
    const int bar_id = chain + 1;     // named barriers 1..4, 64 threads each

    __syncthreads();   // x preload + h init visible CTA-wide

    float h = 0.0f;
    float pr_prev = 0.0f;             // previous step's half-partial of h.w_fc
    int   t_prev  = 0;

    #pragma unroll 1
    for (int s = 0; s < T_LEN; s++) {
        const int t = dir ? (T_LEN - 1 - s) : s;
        const float xt = xrow[t];
        const int p = s & 1;
        const ulonglong2* hv = (const ulonglong2*)hbuf[chain][p];

        // 32 FFMA2 over 4 chains of depth 8; xp folded into a0
        u64 a0 = pack2(fmaf(xt, wih, bias), 0.0f);
        u64 a1 = 0ULL, a2 = 0ULL, a3 = 0ULL;

        #pragma unroll
        for (int j = 0; j < 16; j += 2) {
            const ulonglong2 hA = hv[j];       // broadcast LDS.128
            const ulonglong2 hB = hv[j + 1];
            a0 = ffma2(Wp[2 * j],     hA.x, a0);
            a1 = ffma2(Wp[2 * j + 1], hA.y, a1);
            a2 = ffma2(Wp[2 * j + 2], hB.x, a2);
            a3 = ffma2(Wp[2 * j + 3], hB.y, a3);
        }

        // ---- pipelined SHFL reduction of PREVIOUS step's half-partial ----
        float red = pr_prev;
        #pragma unroll
        for (int o = 16; o; o >>= 1) red += __shfl_xor_sync(0xffffffffu, red, o);
        if (lane == 0 && s > 0) st_cs(&g_row[t_prev], red);

        float lo, hi;
        const u64 d = fadd2(fadd2(a0, a1), fadd2(a2, a3));
        unpack2(d, lo, hi);
        const float z = lo + hi;

        h = fast_tanh(z);
        hbuf[chain][p ^ 1][r] = h;

        pr_prev = h * wfc;
        t_prev  = t;

        // per-chain barrier: pairs warps 2c/2c+1 only; drains STS
        asm volatile("bar.sync %0, 64;" :: "r"(bar_id) : "memory");
    }

    // flush final step's half-partial
    {
        float red = pr_prev;
        #pragma unroll
        for (int o = 16; o; o >>= 1) red += __shfl_xor_sync(0xffffffffu, red, o);
        if (lane == 0) st_cs(&g_row[t_prev], red);
    }

    // final hidden states: h_n[dir][batch][r]
    out[Y_SIZE + dir * (B_SZ * HDIM) + batch * HDIM + r] = h;

    __syncthreads();   // CTA-scope: g_sh writes from all 8 warps visible

    // ---- epilogue: y[b][t] = sigmoid(0.5*((sf0+sf1)+(sb0+sb1)) + b_fc) ----
    const float bfc = b_fc[0];
    for (int m = tid; m < 2 * T_LEN; m += 256) {
        const int blc = m >> 11;            // T_LEN == 2048
        const int t   = m & (T_LEN - 1);
        const int bg  = bb * 2 + blc;
        const int if_ = (0 * B_SZ + bg) * T_LEN + t;
        const int ib_ = (1 * B_SZ + bg) * T_LEN + t;
        const float sf = g_sh[if_] + g_sh[HALF_OFF + if_];
        const float sb = g_sh[ib_] + g_sh[HALF_OFF + ib_];
        const float sv = 0.5f * (sf + sb) + bfc;
        out[bg * T_LEN + t] = __fdividef(1.0f, 1.0f + __expf(-sv));
    }
}

extern "C" void kernel_launch(void* const* d_in, const int* in_sizes, int n_in,
                              void* d_out, int out_size) {
    birnn_kernel<<<128, 256>>>(
        (const float*)d_in[0],                         // x [B,T,1]
        (const float*)d_in[1], (const float*)d_in[2],  // w_ih_f, w_hh_f
        (const float*)d_in[3], (const float*)d_in[4],  // b_ih_f, b_hh_f
        (const float*)d_in[5], (const float*)d_in[6],  // w_ih_b, w_hh_b
        (const float*)d_in[7], (const float*)d_in[8],  // b_ih_b, b_hh_b
        (const float*)d_in[9], (const float*)d_in[10], // w_fc, b_fc
        (float*)d_out);
}

// round 13
// speedup vs baseline: 1.4154x; 1.4154x over previous
#include <cuda_runtime.h>

#define T_LEN 2048
#define B_SZ  256
#define HDIM  64
#define Y_SIZE (B_SZ * T_LEN)

typedef unsigned long long u64;

// scratch for per-(dir,batch,t) scalar projections s = h . w_fc
__device__ float g_s[2 * B_SZ * T_LEN];

__device__ __forceinline__ u64 ffma2(u64 a, u64 b, u64 c) {
    u64 d;
    asm("fma.rn.f32x2 %0, %1, %2, %3;" : "=l"(d) : "l"(a), "l"(b), "l"(c));
    return d;
}
__device__ __forceinline__ u64 fadd2(u64 a, u64 b) {
    u64 d;
    asm("add.rn.f32x2 %0, %1, %2;" : "=l"(d) : "l"(a), "l"(b));
    return d;
}
__device__ __forceinline__ u64 pack2(float lo, float hi) {
    u64 r;
    asm("mov.b64 %0, {%1, %2};" : "=l"(r) : "f"(lo), "f"(hi));
    return r;
}
__device__ __forceinline__ void unpack2(u64 v, float& lo, float& hi) {
    asm("mov.b64 {%0, %1}, %2;" : "=f"(lo), "=f"(hi) : "l"(v));
}
__device__ __forceinline__ float fast_tanh(float z) {
    float e = __expf(2.0f * z);
    return 1.0f - __fdividef(2.0f, e + 1.0f);
}
__device__ __forceinline__ void st_cs(float* p, float v) {
    asm volatile("st.global.cs.f32 [%0], %1;" :: "l"(p), "f"(v) : "memory");
}

__global__ __launch_bounds__(128, 1)
void birnn_kernel(const float* __restrict__ x,
                  const float* __restrict__ w_ih_f, const float* __restrict__ w_hh_f,
                  const float* __restrict__ b_ih_f, const float* __restrict__ b_hh_f,
                  const float* __restrict__ w_ih_b, const float* __restrict__ w_hh_b,
                  const float* __restrict__ b_ih_b, const float* __restrict__ b_hh_b,
                  const float* __restrict__ w_fc,  const float* __restrict__ b_fc,
                  float* __restrict__ out)
{
    __shared__ __align__(16) float xsh[2][T_LEN];        // two batch rows of x
    __shared__ __align__(16) float hbuf[4][2][HDIM];     // per-warp double-buffered h

    const int tid  = threadIdx.x;
    const int wid  = tid >> 5;        // 0..3 -> distinct SMSPs
    const int lane = tid & 31;
    const int bb   = blockIdx.x;      // 0..127
    const int bl   = wid >> 1;        // batch-local 0/1
    const int dir  = wid & 1;         // 0 fwd, 1 bwd
    const int batch = bb * 2 + bl;

    // ---- preload the two x rows into SMEM (cooperative, float4) ----
    {
        const float4* xg = (const float4*)(x + (bb * 2) * T_LEN);
        float4* xs = (float4*)xsh;
        for (int i = tid; i < (2 * T_LEN) / 4; i += 128) xs[i] = xg[i];
    }

    // zero initial hidden state (buffer 0)
    hbuf[wid][0][lane]      = 0.0f;
    hbuf[wid][0][lane + 32] = 0.0f;

    // ---- per-direction parameters ----
    const float* w_ih = dir ? w_ih_b : w_ih_f;
    const float* w_hh = dir ? w_hh_b : w_hh_f;
    const float* b_ih = dir ? b_ih_b : b_ih_f;
    const float* b_hh = dir ? b_hh_b : b_hh_f;

    const int r0 = lane, r1 = lane + 32;
    const float wih0  = w_ih[r0],  wih1  = w_ih[r1];
    const float bias0 = b_ih[r0] + b_hh[r0];
    const float bias1 = b_ih[r1] + b_hh[r1];
    const float wfc0  = w_fc[r0],  wfc1  = w_fc[r1];

    // W_hh rows r0, r1 as packed f32-pairs in registers (128 regs)
    u64 Wp0[32], Wp1[32];
    {
        const u64* wr0 = (const u64*)(w_hh + r0 * HDIM);  // 256B-aligned rows
        const u64* wr1 = (const u64*)(w_hh + r1 * HDIM);
        #pragma unroll
        for (int k = 0; k < 32; k++) { Wp0[k] = wr0[k]; Wp1[k] = wr1[k]; }
    }

    float* g_row = g_s + (dir * B_SZ + batch) * T_LEN;
    const float* xrow = xsh[bl];

    // static ping/pong views of the h exchange buffer
    const ulonglong2* hv0 = (const ulonglong2*)hbuf[wid][0];
    const ulonglong2* hv1 = (const ulonglong2*)hbuf[wid][1];
    float* hw0 = hbuf[wid][0];
    float* hw1 = hbuf[wid][1];

    __syncthreads();   // x preload + h init visible

    float h0 = 0.0f, h1 = 0.0f;
    float pr_prev = 0.0f;          // previous step's un-reduced w_fc partial
    int   t_prev  = 0;

    // One recurrence step. Reduction of the PREVIOUS step's partial is issued
    // FIRST so its 5x26-cyc SHFL chain runs underneath the LDS+FFMA2 block.
#define RNN_STEP(HV, HW, SCUR)                                                  \
    {                                                                           \
        const int t = dir ? (T_LEN - 1 - (SCUR)) : (SCUR);                      \
        /* pipelined reduction (off the serial path) */                         \
        float red = pr_prev;                                                    \
        _Pragma("unroll")                                                       \
        for (int o = 16; o; o >>= 1) red += __shfl_xor_sync(0xffffffffu, red, o); \
        const float xt = xrow[t];                                               \
        u64 a0 = pack2(fmaf(xt, wih0, bias0), 0.0f);                            \
        u64 a1 = pack2(fmaf(xt, wih1, bias1), 0.0f);                            \
        u64 c0 = 0ULL, c1 = 0ULL;                                               \
        _Pragma("unroll")                                                       \
        for (int k = 0; k < 16; k++) {                                          \
            const ulonglong2 h2 = (HV)[k];      /* broadcast LDS.128 */         \
            a0 = ffma2(Wp0[2 * k],     h2.x, a0);                               \
            c0 = ffma2(Wp0[2 * k + 1], h2.y, c0);                               \
            a1 = ffma2(Wp1[2 * k],     h2.x, a1);                               \
            c1 = ffma2(Wp1[2 * k + 1], h2.y, c1);                               \
        }                                                                       \
        if (lane == 0 && (SCUR) > 0) st_cs(&g_row[t_prev], red);                \
        float lo, hi;                                                           \
        u64 d0 = fadd2(a0, c0); unpack2(d0, lo, hi); const float z0 = lo + hi;  \
        u64 d1 = fadd2(a1, c1); unpack2(d1, lo, hi); const float z1 = lo + hi;  \
        h0 = fast_tanh(z0);                                                     \
        h1 = fast_tanh(z1);                                                     \
        (HW)[r0] = h0;                                                          \
        (HW)[r1] = h1;                                                          \
        pr_prev = fmaf(h1, wfc1, h0 * wfc0);                                    \
        t_prev  = t;                                                            \
        __syncwarp();                                                           \
    }

    #pragma unroll 1
    for (int s2 = 0; s2 < T_LEN; s2 += 2) {
        RNN_STEP(hv0, hw1, s2);       // read buf0, write buf1
        RNN_STEP(hv1, hw0, s2 + 1);   // read buf1, write buf0
    }
#undef RNN_STEP

    // flush final step's reduction
    {
        float red = pr_prev;
        #pragma unroll
        for (int o = 16; o; o >>= 1) red += __shfl_xor_sync(0xffffffffu, red, o);
        if (lane == 0) st_cs(&g_row[t_prev], red);
    }

    // final hidden states: h_n[dir][batch][i]
    out[Y_SIZE + dir * (B_SZ * HDIM) + batch * HDIM + r0] = h0;
    out[Y_SIZE + dir * (B_SZ * HDIM) + batch * HDIM + r1] = h1;

    __syncthreads();   // CTA-scope: g_s writes from all 4 warps visible

    // ---- epilogue: y[b][t] = sigmoid(0.5*(s_f+s_b) + b_fc) ----
    const float bfc = b_fc[0];
    for (int m = tid; m < 2 * T_LEN; m += 128) {
        const int blc = m >> 11;           // T_LEN == 2048
        const int t   = m & (T_LEN - 1);
        const int bg  = bb * 2 + blc;
        const float sf = g_s[(0 * B_SZ + bg) * T_LEN + t];
        const float sb = g_s[(1 * B_SZ + bg) * T_LEN + t];
        const float sv = 0.5f * (sf + sb) + bfc;
        out[bg * T_LEN + t] = __fdividef(1.0f, 1.0f + __expf(-sv));
    }
}

extern "C" void kernel_launch(void* const* d_in, const int* in_sizes, int n_in,
                              void* d_out, int out_size) {
    birnn_kernel<<<128, 128>>>(
        (const float*)d_in[0],                         // x [B,T,1]
        (const float*)d_in[1], (const float*)d_in[2],  // w_ih_f, w_hh_f
        (const float*)d_in[3], (const float*)d_in[4],  // b_ih_f, b_hh_f
        (const float*)d_in[5], (const float*)d_in[6],  // w_ih_b, w_hh_b
        (const float*)d_in[7], (const float*)d_in[8],  // b_ih_b, b_hh_b
        (const float*)d_in[9], (const float*)d_in[10], // w_fc, b_fc
        (float*)d_out);
}